// round 5
// baseline (speedup 1.0000x reference)
#include <cuda_runtime.h>
#include <cuda_fp16.h>
#include <cstdint>

#define N_NODES 100000
#define NE      1600000
#define ETOT    (NE + N_NODES)
#define NG      256
#define IN_DIM  480
#define HID     128
#define HEADS   4
#define NEG_SLOPE 0.2f
#define LN_EPS 1e-5f
#define ESHIFT 20.0f
#define FULLMASK 0xffffffffu

// ---------------- scratch (static device globals; no allocation) ----------------
__device__ __align__(16) float  g_h  [N_NODES * HID];   // fp32 running features
__device__ __align__(16) __half g_hh [N_NODES * HID];   // fp16 copy of h (GEMM A operand)
__device__ __align__(16) __half g_hph[N_NODES * HID];   // fp16 projected features (gather operand)
__device__ __align__(16) __half g_wh [(IN_DIM + 3 * HID) * HID]; // n-major fp16 weights
__device__ __align__(16) float g_asrc[N_NODES * HEADS];
__device__ __align__(16) float g_adst[N_NODES * HEADS];
__device__ int g_deg[N_NODES];
__device__ int g_rowptr[N_NODES + 1];
__device__ int g_cursor[N_NODES];
__device__ int g_csr_src[ETOT];
__device__ int g_bsums[256];
__device__ int g_gcnt[NG];
__device__ int g_gstart[NG + 1];

// ---------------- weight prep: transpose to n-major fp16 ----------------
__global__ void k_prepw(const float* __restrict__ Win, const float* __restrict__ Wg) {
    int i = blockIdx.x * blockDim.x + threadIdx.x;
    if (i < IN_DIM * HID) {
        int n = i / IN_DIM, k = i % IN_DIM;
        g_wh[i] = __float2half(Win[k * HID + n]);
    } else {
        int j = i - IN_DIM * HID;
        if (j < 3 * HID * HID) {
            int l = j >> 14, r = j & 16383;
            int n = r >> 7, k = r & 127;
            g_wh[IN_DIM * HID + j] = __float2half(Wg[(l << 14) + k * HID + n]);
        }
    }
}

// ---------------- CSR build ----------------
__global__ void k_zero() {
    int i = blockIdx.x * blockDim.x + threadIdx.x;
    if (i < N_NODES) g_deg[i] = 0;
    if (i < NG) g_gcnt[i] = 0;
}

__global__ void k_ehist(const int* __restrict__ ei) {
    int i = blockIdx.x * blockDim.x + threadIdx.x;
    if (i >= ETOT) return;
    int d = (i < NE) ? ei[NE + i] : (i - NE);
    atomicAdd(&g_deg[d], 1);
}

__global__ void k_ghist(const int* __restrict__ batch) {
    int i = blockIdx.x * blockDim.x + threadIdx.x;
    if (i < N_NODES) atomicAdd(&g_gcnt[batch[i]], 1);
}

#define SCAN_B 512
__global__ void k_scan1() {
    __shared__ int sm[SCAN_B];
    int t = threadIdx.x;
    int i = blockIdx.x * SCAN_B + t;
    int v = (i < N_NODES) ? g_deg[i] : 0;
    sm[t] = v; __syncthreads();
    for (int o = 1; o < SCAN_B; o <<= 1) {
        int u = (t >= o) ? sm[t - o] : 0;
        __syncthreads();
        sm[t] += u;
        __syncthreads();
    }
    if (i < N_NODES) g_rowptr[i + 1] = sm[t];
    if (t == SCAN_B - 1) g_bsums[blockIdx.x] = sm[t];
}

__global__ void k_scan2(int nb) {
    __shared__ int sm[256];
    int t = threadIdx.x;
    int v = (t < nb) ? g_bsums[t] : 0;
    sm[t] = v; __syncthreads();
    for (int o = 1; o < 256; o <<= 1) {
        int u = (t >= o) ? sm[t - o] : 0;
        __syncthreads();
        sm[t] += u;
        __syncthreads();
    }
    if (t < nb) g_bsums[t] = sm[t] - v;  // exclusive
}

__global__ void k_scan3() {
    int i = blockIdx.x * SCAN_B + threadIdx.x;
    if (i < N_NODES) g_rowptr[i + 1] += g_bsums[blockIdx.x];
    if (i == 0) g_rowptr[0] = 0;
}

__global__ void k_cursor() {
    int i = blockIdx.x * blockDim.x + threadIdx.x;
    if (i < N_NODES) g_cursor[i] = g_rowptr[i];
}

__global__ void k_fill(const int* __restrict__ ei) {
    int i = blockIdx.x * blockDim.x + threadIdx.x;
    if (i >= ETOT) return;
    int s, d;
    if (i < NE) { s = ei[i]; d = ei[NE + i]; }
    else        { s = d = i - NE; }
    int pos = atomicAdd(&g_cursor[d], 1);
    g_csr_src[pos] = s;
}

__global__ void k_gscan() {
    __shared__ int sm[NG];
    int t = threadIdx.x;
    int v = g_gcnt[t];
    sm[t] = v; __syncthreads();
    for (int o = 1; o < NG; o <<= 1) {
        int u = (t >= o) ? sm[t - o] : 0;
        __syncthreads();
        sm[t] += u;
        __syncthreads();
    }
    g_gstart[t] = sm[t] - v;
    if (t == NG - 1) g_gstart[NG] = sm[t];
}

// ---------------- fp16 tensor-core GEMM (m16n8k16), 3-stage cp.async ring ----------------
__device__ __forceinline__ unsigned packh2(float a, float b) {
    __half2 h = __floats2half2_rn(a, b);
    return *(unsigned*)&h;
}

__device__ __forceinline__ void mma_f16(float* c, const unsigned* a, const unsigned* b) {
    asm volatile(
        "mma.sync.aligned.m16n8k16.row.col.f32.f16.f16.f32 "
        "{%0,%1,%2,%3},{%4,%5,%6,%7},{%8,%9},{%0,%1,%2,%3};\n"
        : "+f"(c[0]), "+f"(c[1]), "+f"(c[2]), "+f"(c[3])
        : "r"(a[0]), "r"(a[1]), "r"(a[2]), "r"(a[3]), "r"(b[0]), "r"(b[1]));
}

// C[M,128] = A[M,KD] @ B  (B given n-major fp16: Bn[n][k])
// FIRST: A fp32 (x); out = relu(C+bias) -> g_h (fp32) + g_hh (fp16)
// !FIRST: A fp16 (g_hh); out -> g_hph (fp16) + fused per-head scores -> g_asrc/g_adst
template <int KD, bool FIRST>
__global__ __launch_bounds__(256) void gemm16(
    const void* __restrict__ Ap, const __half* __restrict__ Bn,
    const float* __restrict__ bias,
    const float* __restrict__ att_s, const float* __restrict__ att_d)
{
    constexpr int NIT = KD / 16;
    constexpr int ABYTES_ST = FIRST ? (128 * 16 * 4) : (128 * 48);  // per A stage
    __shared__ __align__(16) char Asm[3 * ABYTES_ST];
    __shared__ __align__(16) __half BsH[3][128 * 24];  // rows: 16 halves + 8 pad (48B)

    int tid = threadIdx.x;
    int warp = tid >> 5, lane = tid & 31;
    int wm = warp >> 1, wn = warp & 1;
    int gid = lane >> 2, tg = lane & 3;
    int rowBase = blockIdx.x * 128;

    float acc[2][8][4];
#pragma unroll
    for (int mf = 0; mf < 2; mf++)
#pragma unroll
        for (int nf = 0; nf < 8; nf++)
#pragma unroll
            for (int q = 0; q < 4; q++) acc[mf][nf][q] = 0.f;

    auto loadStage = [&](int st, int it) {
        int k0 = it * 16;
        char* asd = Asm + st * ABYTES_ST;
        if (FIRST) {
            const float* A = (const float*)Ap;
#pragma unroll
            for (int i = 0; i < 2; i++) {
                int id = tid + i * 256;
                int row = id >> 2, seg = id & 3;
                int gr = rowBase + row;
                const float* src = A + (size_t)(gr < N_NODES ? gr : 0) * KD + k0 + seg * 4;
                uint32_t dst = (uint32_t)__cvta_generic_to_shared(
                    asd + (row * 16 + ((seg ^ ((row >> 1) & 3)) << 2)) * 4);
                int sz = (gr < N_NODES) ? 16 : 0;
                asm volatile("cp.async.cg.shared.global [%0], [%1], 16, %2;\n"
                             :: "r"(dst), "l"(src), "r"(sz));
            }
        } else {
            const __half* A = (const __half*)Ap;
            int row = tid >> 1, h16 = tid & 1;
            int gr = rowBase + row;
            const __half* src = A + (size_t)(gr < N_NODES ? gr : 0) * KD + k0 + h16 * 8;
            uint32_t dst = (uint32_t)__cvta_generic_to_shared(asd + row * 48 + h16 * 16);
            int sz = (gr < N_NODES) ? 16 : 0;
            asm volatile("cp.async.cg.shared.global [%0], [%1], 16, %2;\n"
                         :: "r"(dst), "l"(src), "r"(sz));
        }
        {   // B tile: 128 rows x 32B
            int row = tid >> 1, h16 = tid & 1;
            const __half* src = Bn + (size_t)row * KD + k0 + h16 * 8;
            uint32_t dst = (uint32_t)__cvta_generic_to_shared(
                (char*)BsH[st] + row * 48 + h16 * 16);
            asm volatile("cp.async.cg.shared.global [%0], [%1], 16;\n"
                         :: "r"(dst), "l"(src));
        }
        asm volatile("cp.async.commit_group;\n");
    };

    loadStage(0, 0);
    loadStage(1, 1);
    for (int it = 0; it < NIT; it++) {
        if (it < NIT - 1) asm volatile("cp.async.wait_group 1;\n");
        else              asm volatile("cp.async.wait_group 0;\n");
        __syncthreads();
        if (it + 2 < NIT) loadStage((it + 2) % 3, it + 2);

        int st = it % 3;
        char* asd = Asm + st * ABYTES_ST;
        const __half* bs = BsH[st];

        unsigned afr[2][4];
        unsigned bfr[8][2];
#pragma unroll
        for (int mf = 0; mf < 2; mf++) {
            int mB = wm * 32 + mf * 16 + gid;
#pragma unroll
            for (int q = 0; q < 4; q++) {
                int m = mB + (q & 1) * 8;
                if (FIRST) {
                    int k = tg * 2 + (q >> 1) * 8;
                    int seg = k >> 2;
                    const float* p = (const float*)asd +
                        m * 16 + ((seg ^ ((m >> 1) & 3)) << 2) + (k & 3);
                    float2 v = *(const float2*)p;
                    afr[mf][q] = packh2(v.x, v.y);
                } else {
                    afr[mf][q] = *(const unsigned*)(asd + m * 48 + tg * 4 + (q >> 1) * 16);
                }
            }
        }
#pragma unroll
        for (int nf = 0; nf < 8; nf++) {
            int n = wn * 64 + nf * 8 + gid;
            bfr[nf][0] = *(const unsigned*)((const char*)bs + n * 48 + tg * 4);
            bfr[nf][1] = *(const unsigned*)((const char*)bs + n * 48 + tg * 4 + 16);
        }
#pragma unroll
        for (int mf = 0; mf < 2; mf++)
#pragma unroll
            for (int nf = 0; nf < 8; nf++)
                mma_f16(acc[mf][nf], afr[mf], bfr[nf]);
    }

    // ---------------- epilogue ----------------
    if (FIRST) {
#pragma unroll
        for (int mf = 0; mf < 2; mf++) {
            int r0 = rowBase + wm * 32 + mf * 16 + gid;
#pragma unroll
            for (int nf = 0; nf < 8; nf++) {
                int c = wn * 64 + nf * 8 + tg * 2;
                float b0 = __ldg(bias + c), b1 = __ldg(bias + c + 1);
                float u0 = fmaxf(acc[mf][nf][0] + b0, 0.f), u1 = fmaxf(acc[mf][nf][1] + b1, 0.f);
                float u2 = fmaxf(acc[mf][nf][2] + b0, 0.f), u3 = fmaxf(acc[mf][nf][3] + b1, 0.f);
                if (r0 < N_NODES) {
                    *(float2*)(g_h + (size_t)r0 * 128 + c) = make_float2(u0, u1);
                    __half2 hh = __floats2half2_rn(u0, u1);
                    *(__half2*)(g_hh + (size_t)r0 * 128 + c) = hh;
                }
                if (r0 + 8 < N_NODES) {
                    *(float2*)(g_h + (size_t)(r0 + 8) * 128 + c) = make_float2(u2, u3);
                    __half2 hh = __floats2half2_rn(u2, u3);
                    *(__half2*)(g_hh + (size_t)(r0 + 8) * 128 + c) = hh;
                }
            }
        }
    } else {
        float ss[2][2][2] = {}, sd[2][2][2] = {};
#pragma unroll
        for (int nf = 0; nf < 8; nf++) {
            int c = wn * 64 + nf * 8 + tg * 2;
            int hl = nf >> 2;
            float as0 = __ldg(att_s + c), as1 = __ldg(att_s + c + 1);
            float ad0 = __ldg(att_d + c), ad1 = __ldg(att_d + c + 1);
#pragma unroll
            for (int mf = 0; mf < 2; mf++) {
                int r0 = rowBase + wm * 32 + mf * 16 + gid;
                if (r0 < N_NODES)
                    *(__half2*)(g_hph + (size_t)r0 * 128 + c) =
                        __floats2half2_rn(acc[mf][nf][0], acc[mf][nf][1]);
                if (r0 + 8 < N_NODES)
                    *(__half2*)(g_hph + (size_t)(r0 + 8) * 128 + c) =
                        __floats2half2_rn(acc[mf][nf][2], acc[mf][nf][3]);
                ss[mf][0][hl] += acc[mf][nf][0] * as0 + acc[mf][nf][1] * as1;
                ss[mf][1][hl] += acc[mf][nf][2] * as0 + acc[mf][nf][3] * as1;
                sd[mf][0][hl] += acc[mf][nf][0] * ad0 + acc[mf][nf][1] * ad1;
                sd[mf][1][hl] += acc[mf][nf][2] * ad0 + acc[mf][nf][3] * ad1;
            }
        }
#pragma unroll
        for (int mf = 0; mf < 2; mf++)
#pragma unroll
            for (int rs = 0; rs < 2; rs++)
#pragma unroll
                for (int hl = 0; hl < 2; hl++) {
                    float v = ss[mf][rs][hl];
                    v += __shfl_xor_sync(FULLMASK, v, 1);
                    v += __shfl_xor_sync(FULLMASK, v, 2);
                    ss[mf][rs][hl] = v;
                    float w = sd[mf][rs][hl];
                    w += __shfl_xor_sync(FULLMASK, w, 1);
                    w += __shfl_xor_sync(FULLMASK, w, 2);
                    sd[mf][rs][hl] = w;
                }
        if (tg == 0) {
#pragma unroll
            for (int mf = 0; mf < 2; mf++)
#pragma unroll
                for (int rs = 0; rs < 2; rs++) {
                    int r = rowBase + wm * 32 + mf * 16 + rs * 8 + gid;
                    if (r < N_NODES) {
                        g_asrc[r * 4 + wn * 2 + 0] = ss[mf][rs][0];
                        g_asrc[r * 4 + wn * 2 + 1] = ss[mf][rs][1];
                        g_adst[r * 4 + wn * 2 + 0] = sd[mf][rs][0];
                        g_adst[r * 4 + wn * 2 + 1] = sd[mf][rs][1];
                    }
                }
        }
    }
}

// ---------------- fused GAT aggregation + bias + LN + relu + residual ----------------
__device__ __forceinline__ float lrelu(float x) { return x > 0.f ? x : NEG_SLOPE * x; }

__global__ __launch_bounds__(256) void k_agg(
    const float* __restrict__ bgat, const float* __restrict__ lng, const float* __restrict__ lnb)
{
    __shared__ float s_ex[8][128];
    __shared__ int   s_src[8][32];
    int warp = threadIdx.x >> 5, lane = threadIdx.x & 31;
    int n = blockIdx.x * 8 + warp;
    if (n >= N_NODES) return;
    int myh = lane >> 3;
    int beg = g_rowptr[n], end = g_rowptr[n + 1];
    float4 adst4 = *(const float4*)(g_adst + n * 4);

    float a0 = 0.f, a1 = 0.f, a2 = 0.f, a3 = 0.f, den = 0.f;
    float c0 = 0.f, c1 = 0.f, c2 = 0.f, c3 = 0.f, den2 = 0.f;
    for (int jb = beg; jb < end; jb += 32) {
        int j = jb + lane;
        bool v = j < end;
        int s = v ? g_csr_src[j] : 0;
        float4 a4 = *(const float4*)(g_asrc + s * 4);
        float e0 = v ? __expf(lrelu(a4.x + adst4.x) - ESHIFT) : 0.f;
        float e1 = v ? __expf(lrelu(a4.y + adst4.y) - ESHIFT) : 0.f;
        float e2 = v ? __expf(lrelu(a4.z + adst4.z) - ESHIFT) : 0.f;
        float e3 = v ? __expf(lrelu(a4.w + adst4.w) - ESHIFT) : 0.f;
        s_src[warp][lane] = s;
        *(float4*)&s_ex[warp][lane * 4] = make_float4(e0, e1, e2, e3);
        __syncwarp();
        int cnt = min(32, end - jb);
#pragma unroll 4
        for (int k = 0; k < cnt; k += 2) {
            int  sA = s_src[warp][k];
            float eA = s_ex[warp][k * 4 + myh];
            uint2 hvA = *(const uint2*)(g_hph + (size_t)sA * 128 + lane * 4);
            int  kB = (k + 1 < cnt) ? (k + 1) : k;
            float eB = (k + 1 < cnt) ? s_ex[warp][kB * 4 + myh] : 0.f;
            int  sB = s_src[warp][kB];
            uint2 hvB = *(const uint2*)(g_hph + (size_t)sB * 128 + lane * 4);

            float2 loA = __half22float2(*(__half2*)&hvA.x);
            float2 hiA = __half22float2(*(__half2*)&hvA.y);
            a0 = fmaf(eA, loA.x, a0);
            a1 = fmaf(eA, loA.y, a1);
            a2 = fmaf(eA, hiA.x, a2);
            a3 = fmaf(eA, hiA.y, a3);
            den += eA;

            float2 loB = __half22float2(*(__half2*)&hvB.x);
            float2 hiB = __half22float2(*(__half2*)&hvB.y);
            c0 = fmaf(eB, loB.x, c0);
            c1 = fmaf(eB, loB.y, c1);
            c2 = fmaf(eB, hiB.x, c2);
            c3 = fmaf(eB, hiB.y, c3);
            den2 += eB;
        }
        __syncwarp();
    }
    a0 += c0; a1 += c1; a2 += c2; a3 += c3; den += den2;

    float inv = 1.f / fmaxf(den, 1e-38f);
    float4 bg = *(const float4*)(bgat + lane * 4);
    float v0 = a0 * inv + bg.x;
    float v1 = a1 * inv + bg.y;
    float v2 = a2 * inv + bg.z;
    float v3 = a3 * inv + bg.w;

    float s1 = v0 + v1 + v2 + v3;
#pragma unroll
    for (int o = 16; o > 0; o >>= 1) s1 += __shfl_xor_sync(FULLMASK, s1, o);
    float mu = s1 * (1.f / 128.f);
    float d0 = v0 - mu, d1 = v1 - mu, d2 = v2 - mu, d3 = v3 - mu;
    float s2 = d0 * d0 + d1 * d1 + d2 * d2 + d3 * d3;
#pragma unroll
    for (int o = 16; o > 0; o >>= 1) s2 += __shfl_xor_sync(FULLMASK, s2, o);
    float r = rsqrtf(s2 * (1.f / 128.f) + LN_EPS);
    float4 g4 = *(const float4*)(lng + lane * 4);
    float4 b4 = *(const float4*)(lnb + lane * 4);
    float o0 = fmaxf(d0 * r * g4.x + b4.x, 0.f);
    float o1 = fmaxf(d1 * r * g4.y + b4.y, 0.f);
    float o2 = fmaxf(d2 * r * g4.z + b4.z, 0.f);
    float o3 = fmaxf(d3 * r * g4.w + b4.w, 0.f);
    float4 res = *(const float4*)(g_h + (size_t)n * 128 + lane * 4);
    float4 outv = make_float4(o0 + res.x, o1 + res.y, o2 + res.z, o3 + res.w);
    *(float4*)(g_h + (size_t)n * 128 + lane * 4) = outv;
    __half2 p0 = __floats2half2_rn(outv.x, outv.y);
    __half2 p1 = __floats2half2_rn(outv.z, outv.w);
    uint2 pk = make_uint2(*(unsigned*)&p0, *(unsigned*)&p1);
    *(uint2*)(g_hh + (size_t)n * 128 + lane * 4) = pk;
}

// ---------------- per-graph mean pooling ----------------
__global__ void k_pool(float* __restrict__ out) {
    int g = blockIdx.x;
    int d = threadIdx.x;  // 128 threads
    int s = g_gstart[g], e = g_gstart[g + 1];
    float acc0 = 0.f, acc1 = 0.f;
    int nn = s;
    for (; nn + 1 < e; nn += 2) {
        acc0 += g_h[(size_t)nn * 128 + d];
        acc1 += g_h[(size_t)(nn + 1) * 128 + d];
    }
    if (nn < e) acc0 += g_h[(size_t)nn * 128 + d];
    out[g * 128 + d] = (acc0 + acc1) / fmaxf((float)(e - s), 1.f);
}

// ---------------- launch ----------------
extern "C" void kernel_launch(void* const* d_in, const int* in_sizes, int n_in,
                              void* d_out, int out_size)
{
    const float* x       = (const float*)d_in[0];
    const float* W_in    = (const float*)d_in[1];
    const float* b_in    = (const float*)d_in[2];
    const float* W_gat   = (const float*)d_in[3];
    const float* att_src = (const float*)d_in[4];
    const float* att_dst = (const float*)d_in[5];
    const float* b_gat   = (const float*)d_in[6];
    const float* ln_g    = (const float*)d_in[7];
    const float* ln_b    = (const float*)d_in[8];
    const int*   ei      = (const int*)d_in[9];
    const int*   batch   = (const int*)d_in[10];
    float* out = (float*)d_out;

    __half* hh; cudaGetSymbolAddress((void**)&hh, g_hh);
    __half* wh; cudaGetSymbolAddress((void**)&wh, g_wh);

    static cudaStream_t side = nullptr;
    static cudaEvent_t evF = nullptr, evJ = nullptr;
    if (!side) {
        cudaStreamCreateWithFlags(&side, cudaStreamNonBlocking);
        cudaEventCreateWithFlags(&evF, cudaEventDisableTiming);
        cudaEventCreateWithFlags(&evJ, cudaEventDisableTiming);
    }

    const int nscan = (N_NODES + SCAN_B - 1) / SCAN_B;
    const int nprep = (IN_DIM + 3 * HID) * HID;

    // fork: CSR build on side stream; prep + GEMM1 on main stream
    cudaEventRecord(evF, 0);
    cudaStreamWaitEvent(side, evF, 0);
    k_zero<<<(N_NODES + 255) / 256, 256, 0, side>>>();
    k_ehist<<<(ETOT + 255) / 256, 256, 0, side>>>(ei);
    k_ghist<<<(N_NODES + 255) / 256, 256, 0, side>>>(batch);
    k_scan1<<<nscan, SCAN_B, 0, side>>>();
    k_scan2<<<1, 256, 0, side>>>(nscan);
    k_scan3<<<nscan, SCAN_B, 0, side>>>();
    k_cursor<<<(N_NODES + 255) / 256, 256, 0, side>>>();
    k_fill<<<(ETOT + 255) / 256, 256, 0, side>>>(ei);
    k_gscan<<<1, NG, 0, side>>>();
    cudaEventRecord(evJ, side);

    k_prepw<<<(nprep + 255) / 256, 256>>>(W_in, W_gat);
    gemm16<IN_DIM, true><<<(N_NODES + 127) / 128, 256>>>(
        x, wh, b_in, nullptr, nullptr);

    cudaStreamWaitEvent(0, evJ, 0);

    for (int l = 0; l < 3; l++) {
        gemm16<HID, false><<<(N_NODES + 127) / 128, 256>>>(
            hh, wh + IN_DIM * HID + l * HID * HID, nullptr,
            att_src + l * HID, att_dst + l * HID);
        k_agg<<<(N_NODES + 7) / 8, 256>>>(b_gat + l * HID, ln_g + l * HID, ln_b + l * HID);
    }

    k_pool<<<NG, HID>>>(out);
}

// round 6
// speedup vs baseline: 1.0983x; 1.0983x over previous
#include <cuda_runtime.h>
#include <cuda_fp16.h>
#include <cstdint>

#define N_NODES 100000
#define NE      1600000
#define ETOT    (NE + N_NODES)
#define NG      256
#define IN_DIM  480
#define HID     128
#define HEADS   4
#define NEG_SLOPE 0.2f
#define LN_EPS 1e-5f
#define ESHIFT 20.0f
#define FULLMASK 0xffffffffu

// ---------------- scratch (static device globals; no allocation) ----------------
__device__ __align__(16) float  g_h  [N_NODES * HID];   // fp32 running features
__device__ __align__(16) __half g_hh [N_NODES * HID];   // fp16 copy of h (GEMM A operand)
__device__ __align__(16) __half g_hph[N_NODES * HID];   // fp16 projected features (gather operand)
__device__ __align__(16) __half g_wh [(IN_DIM + 3 * HID) * HID]; // n-major fp16 weights
__device__ __align__(16) float g_asrc[N_NODES * HEADS];
__device__ __align__(16) float g_adst[N_NODES * HEADS];
__device__ int g_deg[N_NODES];
__device__ int g_rowptr[N_NODES + 1];
__device__ int g_cursor[N_NODES];
__device__ int g_csr_src[ETOT];
__device__ int g_bsums[256];
__device__ int g_gcnt[NG];
__device__ int g_gstart[NG + 1];

// ---------------- weight prep: transpose to n-major fp16 ----------------
__global__ void k_prepw(const float* __restrict__ Win, const float* __restrict__ Wg) {
    int i = blockIdx.x * blockDim.x + threadIdx.x;
    if (i < IN_DIM * HID) {
        int n = i / IN_DIM, k = i % IN_DIM;
        g_wh[i] = __float2half(Win[k * HID + n]);
    } else {
        int j = i - IN_DIM * HID;
        if (j < 3 * HID * HID) {
            int l = j >> 14, r = j & 16383;
            int n = r >> 7, k = r & 127;
            g_wh[IN_DIM * HID + j] = __float2half(Wg[(l << 14) + k * HID + n]);
        }
    }
}

// ---------------- CSR build ----------------
__global__ void k_zero() {
    int i = blockIdx.x * blockDim.x + threadIdx.x;
    if (i < N_NODES) g_deg[i] = 0;
    if (i < NG) g_gcnt[i] = 0;
}

__global__ void k_ehist(const int* __restrict__ ei) {
    int i = blockIdx.x * blockDim.x + threadIdx.x;
    if (i >= ETOT) return;
    int d = (i < NE) ? ei[NE + i] : (i - NE);
    atomicAdd(&g_deg[d], 1);
}

__global__ void k_ghist(const int* __restrict__ batch) {
    int i = blockIdx.x * blockDim.x + threadIdx.x;
    if (i < N_NODES) atomicAdd(&g_gcnt[batch[i]], 1);
}

#define SCAN_B 512
__global__ void k_scan1() {
    __shared__ int sm[SCAN_B];
    int t = threadIdx.x;
    int i = blockIdx.x * SCAN_B + t;
    int v = (i < N_NODES) ? g_deg[i] : 0;
    sm[t] = v; __syncthreads();
    for (int o = 1; o < SCAN_B; o <<= 1) {
        int u = (t >= o) ? sm[t - o] : 0;
        __syncthreads();
        sm[t] += u;
        __syncthreads();
    }
    if (i < N_NODES) g_rowptr[i + 1] = sm[t];
    if (t == SCAN_B - 1) g_bsums[blockIdx.x] = sm[t];
}

__global__ void k_scan2(int nb) {
    __shared__ int sm[256];
    int t = threadIdx.x;
    int v = (t < nb) ? g_bsums[t] : 0;
    sm[t] = v; __syncthreads();
    for (int o = 1; o < 256; o <<= 1) {
        int u = (t >= o) ? sm[t - o] : 0;
        __syncthreads();
        sm[t] += u;
        __syncthreads();
    }
    if (t < nb) g_bsums[t] = sm[t] - v;  // exclusive
}

__global__ void k_scan3() {
    int i = blockIdx.x * SCAN_B + threadIdx.x;
    if (i < N_NODES) g_rowptr[i + 1] += g_bsums[blockIdx.x];
    if (i == 0) g_rowptr[0] = 0;
}

__global__ void k_cursor() {
    int i = blockIdx.x * blockDim.x + threadIdx.x;
    if (i < N_NODES) g_cursor[i] = g_rowptr[i];
}

__global__ void k_fill(const int* __restrict__ ei) {
    int i = blockIdx.x * blockDim.x + threadIdx.x;
    if (i >= ETOT) return;
    int s, d;
    if (i < NE) { s = ei[i]; d = ei[NE + i]; }
    else        { s = d = i - NE; }
    int pos = atomicAdd(&g_cursor[d], 1);
    g_csr_src[pos] = s;
}

__global__ void k_gscan() {
    __shared__ int sm[NG];
    int t = threadIdx.x;
    int v = g_gcnt[t];
    sm[t] = v; __syncthreads();
    for (int o = 1; o < NG; o <<= 1) {
        int u = (t >= o) ? sm[t - o] : 0;
        __syncthreads();
        sm[t] += u;
        __syncthreads();
    }
    g_gstart[t] = sm[t] - v;
    if (t == NG - 1) g_gstart[NG] = sm[t];
}

// ---------------- fp16 tensor-core GEMM (m16n8k16), 3-stage cp.async ring ----------------
__device__ __forceinline__ unsigned packh2(float a, float b) {
    __half2 h = __floats2half2_rn(a, b);
    return *(unsigned*)&h;
}

__device__ __forceinline__ void mma_f16(float* c, const unsigned* a, const unsigned* b) {
    asm volatile(
        "mma.sync.aligned.m16n8k16.row.col.f32.f16.f16.f32 "
        "{%0,%1,%2,%3},{%4,%5,%6,%7},{%8,%9},{%0,%1,%2,%3};\n"
        : "+f"(c[0]), "+f"(c[1]), "+f"(c[2]), "+f"(c[3])
        : "r"(a[0]), "r"(a[1]), "r"(a[2]), "r"(a[3]), "r"(b[0]), "r"(b[1]));
}

// C[M,128] = A[M,KD] @ B  (B given n-major fp16: Bn[n][k])
// FIRST: A fp32 (x); out = relu(C+bias) -> g_h (fp32) + g_hh (fp16)
// !FIRST: A fp16 (g_hh); out -> g_hph (fp16) + fused per-head scores -> g_asrc/g_adst
template <int KD, bool FIRST>
__global__ __launch_bounds__(256) void gemm16(
    const void* __restrict__ Ap, const __half* __restrict__ Bn,
    const float* __restrict__ bias,
    const float* __restrict__ att_s, const float* __restrict__ att_d)
{
    constexpr int NIT = KD / 16;
    constexpr int ABYTES_ST = FIRST ? (128 * 16 * 4) : (128 * 48);  // per A stage
    __shared__ __align__(16) char Asm[3 * ABYTES_ST];
    __shared__ __align__(16) __half BsH[3][128 * 24];  // rows: 16 halves + 8 pad (48B)

    int tid = threadIdx.x;
    int warp = tid >> 5, lane = tid & 31;
    int wm = warp >> 1, wn = warp & 1;
    int gid = lane >> 2, tg = lane & 3;
    int rowBase = blockIdx.x * 128;

    float acc[2][8][4];
#pragma unroll
    for (int mf = 0; mf < 2; mf++)
#pragma unroll
        for (int nf = 0; nf < 8; nf++)
#pragma unroll
            for (int q = 0; q < 4; q++) acc[mf][nf][q] = 0.f;

    auto loadStage = [&](int st, int it) {
        int k0 = it * 16;
        char* asd = Asm + st * ABYTES_ST;
        if (FIRST) {
            const float* A = (const float*)Ap;
#pragma unroll
            for (int i = 0; i < 2; i++) {
                int id = tid + i * 256;
                int row = id >> 2, seg = id & 3;
                int gr = rowBase + row;
                const float* src = A + (size_t)(gr < N_NODES ? gr : 0) * KD + k0 + seg * 4;
                uint32_t dst = (uint32_t)__cvta_generic_to_shared(
                    asd + (row * 16 + ((seg ^ ((row >> 1) & 3)) << 2)) * 4);
                int sz = (gr < N_NODES) ? 16 : 0;
                asm volatile("cp.async.cg.shared.global [%0], [%1], 16, %2;\n"
                             :: "r"(dst), "l"(src), "r"(sz));
            }
        } else {
            const __half* A = (const __half*)Ap;
            int row = tid >> 1, h16 = tid & 1;
            int gr = rowBase + row;
            const __half* src = A + (size_t)(gr < N_NODES ? gr : 0) * KD + k0 + h16 * 8;
            uint32_t dst = (uint32_t)__cvta_generic_to_shared(asd + row * 48 + h16 * 16);
            int sz = (gr < N_NODES) ? 16 : 0;
            asm volatile("cp.async.cg.shared.global [%0], [%1], 16, %2;\n"
                         :: "r"(dst), "l"(src), "r"(sz));
        }
        {   // B tile: 128 rows x 32B
            int row = tid >> 1, h16 = tid & 1;
            const __half* src = Bn + (size_t)row * KD + k0 + h16 * 8;
            uint32_t dst = (uint32_t)__cvta_generic_to_shared(
                (char*)BsH[st] + row * 48 + h16 * 16);
            asm volatile("cp.async.cg.shared.global [%0], [%1], 16;\n"
                         :: "r"(dst), "l"(src));
        }
        asm volatile("cp.async.commit_group;\n");
    };

    loadStage(0, 0);
    loadStage(1, 1);
    for (int it = 0; it < NIT; it++) {
        if (it < NIT - 1) asm volatile("cp.async.wait_group 1;\n");
        else              asm volatile("cp.async.wait_group 0;\n");
        __syncthreads();
        if (it + 2 < NIT) loadStage((it + 2) % 3, it + 2);

        int st = it % 3;
        char* asd = Asm + st * ABYTES_ST;
        const __half* bs = BsH[st];

        unsigned afr[2][4];
        unsigned bfr[8][2];
#pragma unroll
        for (int mf = 0; mf < 2; mf++) {
            int mB = wm * 32 + mf * 16 + gid;
#pragma unroll
            for (int q = 0; q < 4; q++) {
                int m = mB + (q & 1) * 8;
                if (FIRST) {
                    int k = tg * 2 + (q >> 1) * 8;
                    int seg = k >> 2;
                    const float* p = (const float*)asd +
                        m * 16 + ((seg ^ ((m >> 1) & 3)) << 2) + (k & 3);
                    float2 v = *(const float2*)p;
                    afr[mf][q] = packh2(v.x, v.y);
                } else {
                    afr[mf][q] = *(const unsigned*)(asd + m * 48 + tg * 4 + (q >> 1) * 16);
                }
            }
        }
#pragma unroll
        for (int nf = 0; nf < 8; nf++) {
            int n = wn * 64 + nf * 8 + gid;
            bfr[nf][0] = *(const unsigned*)((const char*)bs + n * 48 + tg * 4);
            bfr[nf][1] = *(const unsigned*)((const char*)bs + n * 48 + tg * 4 + 16);
        }
#pragma unroll
        for (int mf = 0; mf < 2; mf++)
#pragma unroll
            for (int nf = 0; nf < 8; nf++)
                mma_f16(acc[mf][nf], afr[mf], bfr[nf]);
    }

    // ---------------- epilogue ----------------
    if (FIRST) {
#pragma unroll
        for (int mf = 0; mf < 2; mf++) {
            int r0 = rowBase + wm * 32 + mf * 16 + gid;
#pragma unroll
            for (int nf = 0; nf < 8; nf++) {
                int c = wn * 64 + nf * 8 + tg * 2;
                float b0 = __ldg(bias + c), b1 = __ldg(bias + c + 1);
                float u0 = fmaxf(acc[mf][nf][0] + b0, 0.f), u1 = fmaxf(acc[mf][nf][1] + b1, 0.f);
                float u2 = fmaxf(acc[mf][nf][2] + b0, 0.f), u3 = fmaxf(acc[mf][nf][3] + b1, 0.f);
                if (r0 < N_NODES) {
                    *(float2*)(g_h + (size_t)r0 * 128 + c) = make_float2(u0, u1);
                    __half2 hh = __floats2half2_rn(u0, u1);
                    *(__half2*)(g_hh + (size_t)r0 * 128 + c) = hh;
                }
                if (r0 + 8 < N_NODES) {
                    *(float2*)(g_h + (size_t)(r0 + 8) * 128 + c) = make_float2(u2, u3);
                    __half2 hh = __floats2half2_rn(u2, u3);
                    *(__half2*)(g_hh + (size_t)(r0 + 8) * 128 + c) = hh;
                }
            }
        }
    } else {
        float ss[2][2][2] = {}, sd[2][2][2] = {};
#pragma unroll
        for (int nf = 0; nf < 8; nf++) {
            int c = wn * 64 + nf * 8 + tg * 2;
            int hl = nf >> 2;
            float as0 = __ldg(att_s + c), as1 = __ldg(att_s + c + 1);
            float ad0 = __ldg(att_d + c), ad1 = __ldg(att_d + c + 1);
#pragma unroll
            for (int mf = 0; mf < 2; mf++) {
                int r0 = rowBase + wm * 32 + mf * 16 + gid;
                if (r0 < N_NODES)
                    *(__half2*)(g_hph + (size_t)r0 * 128 + c) =
                        __floats2half2_rn(acc[mf][nf][0], acc[mf][nf][1]);
                if (r0 + 8 < N_NODES)
                    *(__half2*)(g_hph + (size_t)(r0 + 8) * 128 + c) =
                        __floats2half2_rn(acc[mf][nf][2], acc[mf][nf][3]);
                ss[mf][0][hl] += acc[mf][nf][0] * as0 + acc[mf][nf][1] * as1;
                ss[mf][1][hl] += acc[mf][nf][2] * as0 + acc[mf][nf][3] * as1;
                sd[mf][0][hl] += acc[mf][nf][0] * ad0 + acc[mf][nf][1] * ad1;
                sd[mf][1][hl] += acc[mf][nf][2] * ad0 + acc[mf][nf][3] * ad1;
            }
        }
#pragma unroll
        for (int mf = 0; mf < 2; mf++)
#pragma unroll
            for (int rs = 0; rs < 2; rs++)
#pragma unroll
                for (int hl = 0; hl < 2; hl++) {
                    float v = ss[mf][rs][hl];
                    v += __shfl_xor_sync(FULLMASK, v, 1);
                    v += __shfl_xor_sync(FULLMASK, v, 2);
                    ss[mf][rs][hl] = v;
                    float w = sd[mf][rs][hl];
                    w += __shfl_xor_sync(FULLMASK, w, 1);
                    w += __shfl_xor_sync(FULLMASK, w, 2);
                    sd[mf][rs][hl] = w;
                }
        if (tg == 0) {
#pragma unroll
            for (int mf = 0; mf < 2; mf++)
#pragma unroll
                for (int rs = 0; rs < 2; rs++) {
                    int r = rowBase + wm * 32 + mf * 16 + rs * 8 + gid;
                    if (r < N_NODES) {
                        g_asrc[r * 4 + wn * 2 + 0] = ss[mf][rs][0];
                        g_asrc[r * 4 + wn * 2 + 1] = ss[mf][rs][1];
                        g_adst[r * 4 + wn * 2 + 0] = sd[mf][rs][0];
                        g_adst[r * 4 + wn * 2 + 1] = sd[mf][rs][1];
                    }
                }
        }
    }
}

// ---------------- fused GAT aggregation + bias + LN + relu + residual ----------------
__device__ __forceinline__ float lrelu(float x) { return x > 0.f ? x : NEG_SLOPE * x; }

__global__ __launch_bounds__(256) void k_agg(
    const float* __restrict__ bgat, const float* __restrict__ lng, const float* __restrict__ lnb)
{
    __shared__ float s_ex[8][128];
    __shared__ int   s_src[8][32];
    int warp = threadIdx.x >> 5, lane = threadIdx.x & 31;
    int n = blockIdx.x * 8 + warp;
    if (n >= N_NODES) return;
    int myh = lane >> 3;
    int beg = g_rowptr[n], end = g_rowptr[n + 1];
    float4 adst4 = *(const float4*)(g_adst + n * 4);

    float a0 = 0.f, a1 = 0.f, a2 = 0.f, a3 = 0.f, den = 0.f;
    for (int jb = beg; jb < end; jb += 32) {
        int j = jb + lane;
        bool v = j < end;
        int s = v ? g_csr_src[j] : 0;
        float4 a4 = *(const float4*)(g_asrc + s * 4);
        float e0 = v ? __expf(lrelu(a4.x + adst4.x) - ESHIFT) : 0.f;
        float e1 = v ? __expf(lrelu(a4.y + adst4.y) - ESHIFT) : 0.f;
        float e2 = v ? __expf(lrelu(a4.z + adst4.z) - ESHIFT) : 0.f;
        float e3 = v ? __expf(lrelu(a4.w + adst4.w) - ESHIFT) : 0.f;
        s_src[warp][lane] = s;
        *(float4*)&s_ex[warp][lane * 4] = make_float4(e0, e1, e2, e3);
        __syncwarp();
        int cnt = min(32, end - jb);
#pragma unroll 8
        for (int k = 0; k < cnt; k++) {
            int ss = s_src[warp][k];
            float e = s_ex[warp][k * 4 + myh];
            uint2 hv = *(const uint2*)(g_hph + (size_t)ss * 128 + lane * 4);
            float2 lo = __half22float2(*(__half2*)&hv.x);
            float2 hi = __half22float2(*(__half2*)&hv.y);
            a0 = fmaf(e, lo.x, a0);
            a1 = fmaf(e, lo.y, a1);
            a2 = fmaf(e, hi.x, a2);
            a3 = fmaf(e, hi.y, a3);
            den += e;
        }
        __syncwarp();
    }
    float inv = 1.f / fmaxf(den, 1e-38f);
    float4 bg = *(const float4*)(bgat + lane * 4);
    float v0 = a0 * inv + bg.x;
    float v1 = a1 * inv + bg.y;
    float v2 = a2 * inv + bg.z;
    float v3 = a3 * inv + bg.w;

    float s1 = v0 + v1 + v2 + v3;
#pragma unroll
    for (int o = 16; o > 0; o >>= 1) s1 += __shfl_xor_sync(FULLMASK, s1, o);
    float mu = s1 * (1.f / 128.f);
    float d0 = v0 - mu, d1 = v1 - mu, d2 = v2 - mu, d3 = v3 - mu;
    float s2 = d0 * d0 + d1 * d1 + d2 * d2 + d3 * d3;
#pragma unroll
    for (int o = 16; o > 0; o >>= 1) s2 += __shfl_xor_sync(FULLMASK, s2, o);
    float r = rsqrtf(s2 * (1.f / 128.f) + LN_EPS);
    float4 g4 = *(const float4*)(lng + lane * 4);
    float4 b4 = *(const float4*)(lnb + lane * 4);
    float o0 = fmaxf(d0 * r * g4.x + b4.x, 0.f);
    float o1 = fmaxf(d1 * r * g4.y + b4.y, 0.f);
    float o2 = fmaxf(d2 * r * g4.z + b4.z, 0.f);
    float o3 = fmaxf(d3 * r * g4.w + b4.w, 0.f);
    float4 res = *(const float4*)(g_h + (size_t)n * 128 + lane * 4);
    float4 outv = make_float4(o0 + res.x, o1 + res.y, o2 + res.z, o3 + res.w);
    *(float4*)(g_h + (size_t)n * 128 + lane * 4) = outv;
    __half2 p0 = __floats2half2_rn(outv.x, outv.y);
    __half2 p1 = __floats2half2_rn(outv.z, outv.w);
    uint2 pk = make_uint2(*(unsigned*)&p0, *(unsigned*)&p1);
    *(uint2*)(g_hh + (size_t)n * 128 + lane * 4) = pk;
}

// ---------------- per-graph mean pooling (4 slices/graph, 2-way unroll) ----------------
__global__ __launch_bounds__(512) void k_pool(float* __restrict__ out) {
    __shared__ float red[4][128];
    int g = blockIdx.x;
    int slice = threadIdx.x >> 7;       // 0..3
    int d = threadIdx.x & 127;
    int s = g_gstart[g], e = g_gstart[g + 1];
    float a0 = 0.f, a1 = 0.f;
    int nn = s + slice;
    for (; nn + 4 < e; nn += 8) {
        a0 += g_h[(size_t)nn * 128 + d];
        a1 += g_h[(size_t)(nn + 4) * 128 + d];
    }
    if (nn < e) a0 += g_h[(size_t)nn * 128 + d];
    red[slice][d] = a0 + a1;
    __syncthreads();
    if (slice == 0) {
        float v = red[0][d] + red[1][d] + red[2][d] + red[3][d];
        out[g * 128 + d] = v / fmaxf((float)(e - s), 1.f);
    }
}

// ---------------- launch ----------------
extern "C" void kernel_launch(void* const* d_in, const int* in_sizes, int n_in,
                              void* d_out, int out_size)
{
    const float* x       = (const float*)d_in[0];
    const float* W_in    = (const float*)d_in[1];
    const float* b_in    = (const float*)d_in[2];
    const float* W_gat   = (const float*)d_in[3];
    const float* att_src = (const float*)d_in[4];
    const float* att_dst = (const float*)d_in[5];
    const float* b_gat   = (const float*)d_in[6];
    const float* ln_g    = (const float*)d_in[7];
    const float* ln_b    = (const float*)d_in[8];
    const int*   ei      = (const int*)d_in[9];
    const int*   batch   = (const int*)d_in[10];
    float* out = (float*)d_out;

    __half* hh; cudaGetSymbolAddress((void**)&hh, g_hh);
    __half* wh; cudaGetSymbolAddress((void**)&wh, g_wh);

    static cudaStream_t side = nullptr;
    static cudaEvent_t evF = nullptr, evJ = nullptr;
    if (!side) {
        cudaStreamCreateWithFlags(&side, cudaStreamNonBlocking);
        cudaEventCreateWithFlags(&evF, cudaEventDisableTiming);
        cudaEventCreateWithFlags(&evJ, cudaEventDisableTiming);
    }

    const int nscan = (N_NODES + SCAN_B - 1) / SCAN_B;
    const int nprep = (IN_DIM + 3 * HID) * HID;

    // fork: CSR build on side stream; prep + GEMM1 on main stream
    cudaEventRecord(evF, 0);
    cudaStreamWaitEvent(side, evF, 0);
    k_zero<<<(N_NODES + 255) / 256, 256, 0, side>>>();
    k_ehist<<<(ETOT + 255) / 256, 256, 0, side>>>(ei);
    k_ghist<<<(N_NODES + 255) / 256, 256, 0, side>>>(batch);
    k_scan1<<<nscan, SCAN_B, 0, side>>>();
    k_scan2<<<1, 256, 0, side>>>(nscan);
    k_scan3<<<nscan, SCAN_B, 0, side>>>();
    k_cursor<<<(N_NODES + 255) / 256, 256, 0, side>>>();
    k_fill<<<(ETOT + 255) / 256, 256, 0, side>>>(ei);
    k_gscan<<<1, NG, 0, side>>>();
    cudaEventRecord(evJ, side);

    k_prepw<<<(nprep + 255) / 256, 256>>>(W_in, W_gat);
    gemm16<IN_DIM, true><<<(N_NODES + 127) / 128, 256>>>(
        x, wh, b_in, nullptr, nullptr);

    cudaStreamWaitEvent(0, evJ, 0);

    for (int l = 0; l < 3; l++) {
        gemm16<HID, false><<<(N_NODES + 127) / 128, 256>>>(
            hh, wh + IN_DIM * HID + l * HID * HID, nullptr,
            att_src + l * HID, att_dst + l * HID);
        k_agg<<<(N_NODES + 7) / 8, 256>>>(b_gat + l * HID, ln_g + l * HID, ln_b + l * HID);
    }

    k_pool<<<NG, 512>>>(out);
}